// round 10
// baseline (speedup 1.0000x reference)
#include <cuda_runtime.h>

// Problem constants (fixed shapes from the reference setup_inputs)
#define Bq   4
#define Tq   512
#define TPq  1024
#define Cq   32
#define Kq   128
#define EPSF 2.2204460492503131e-16f

// Scratch (__device__ globals — no allocation allowed in kernel_launch)
__device__ float g_sp_delta[Cq * Cq];   // softplus(delta)[e][c] + EPS
__device__ float g_sp_mu[Cq];
__device__ float g_probs[Kq];           // p(fine k | coarse ftc[k])
// Prefix table: G[b][j][e][c], j in [0, T]  (8.4 MB, L2-resident)
__device__ float g_table[(size_t)Bq * (Tq + 1) * Cq * Cq];

__device__ __forceinline__ float softplus_f(float x) {
    // log(1 + e^x), fast version (rel err ~1e-6, tol is 1e-3)
    return (x > 0.0f) ? x + __logf(1.0f + __expf(-x))
                      : __logf(1.0f + __expf(x));
}

// ---------------------------------------------------------------------------
// Kernel 1: build causal prefix table + publish prepped parameters.
//   block = (b, e) pair, 512 threads = 16 warps; lane = channel c,
//   warp w owns j-chunk [w*32, (w+1)*32).
//   G[b][j][e][c] = sum over events i<j with type e of pa[e,c]*exp(pd[e,c]*pt_i)
//   Two-pass chunk scan: pass 1 chunk totals, pass 2 write prefix.
//   Side duties (prep):  b==0,wid==0: g_sp_delta row e
//                        block 0, wid 1: g_sp_mu;  wid 2: grouped softmax
// ---------------------------------------------------------------------------
__global__ void __launch_bounds__(512)
table_kernel(const int*   __restrict__ past_event,
             const float* __restrict__ past_time,
             const float* __restrict__ alpha,
             const float* __restrict__ delta,
             const float* __restrict__ mu,
             const float* __restrict__ cf,
             const int*   __restrict__ ftc) {
    int b   = blockIdx.x / Cq;
    int e   = blockIdx.x % Cq;
    int wid = threadIdx.x >> 5;
    int c   = threadIdx.x & 31;

    __shared__ int   s_ev[Tq];
    __shared__ float s_pt[Tq];
    __shared__ float s_chunk[16][Cq];
    __shared__ float s_den[Cq];

    for (int i = threadIdx.x; i < Tq; i += blockDim.x) {
        s_ev[i] = past_event[b * Tq + i];
        s_pt[i] = past_time[b * Tq + i];
    }

    float pa = softplus_f(alpha[e * Cq + c]);
    float pd = softplus_f(delta[e * Cq + c]) + EPSF;

    // ---- side duties (before first __syncthreads, fully parallel) ----
    if (b == 0 && wid == 0) g_sp_delta[e * Cq + c] = pd;
    if (blockIdx.x == 0) {
        if (wid == 1) g_sp_mu[c] = softplus_f(mu[c]);
        if (wid == 2) {
            // grouped softmax over 128 fine logits (max-shift cancels exactly)
            s_den[c] = 0.0f;
            __syncwarp();
            float ev[4]; int fc[4];
            #pragma unroll
            for (int r = 0; r < 4; r++) {
                int k = r * 32 + c;
                ev[r] = __expf(cf[k]);
                fc[r] = ftc[k];
                atomicAdd(&s_den[fc[r]], ev[r]);
            }
            __syncwarp();
            #pragma unroll
            for (int r = 0; r < 4; r++)
                g_probs[r * 32 + c] = ev[r] / s_den[fc[r]];
        }
    }
    __syncthreads();

    const int CHUNK = Tq / 16;          // 32
    int j0 = wid * CHUNK, j1 = j0 + CHUNK;

    // pass 1: chunk totals (s_ev[j]==e is warp-uniform -> exp only on matches)
    float sum = 0.0f;
    for (int j = j0; j < j1; j++)
        if (s_ev[j] == e) sum += pa * __expf(pd * s_pt[j]);
    s_chunk[wid][c] = sum;
    __syncthreads();

    float off = 0.0f;
    #pragma unroll
    for (int w = 0; w < 16; w++) if (w < wid) off += s_chunk[w][c];

    // pass 2: write exclusive prefix
    float* out = g_table + ((size_t)b * (Tq + 1)) * (Cq * Cq) + e * Cq + c;
    float run = off;
    for (int j = j0; j < j1; j++) {
        out[(size_t)j * (Cq * Cq)] = run;
        if (s_ev[j] == e) run += pa * __expf(pd * s_pt[j]);
    }
    if (wid == 15) out[(size_t)Tq * (Cq * Cq)] = run;
}

// ---------------------------------------------------------------------------
// Kernel 2: queries. TWO queries per warp (2w, 2w+1 — always same batch b).
//   acc[c] = sp_mu[c] + sum_e exp(-pd[e,c]*t') * G[b][j][e][c]
//   Rank search: round 1 one load + two ballots; round 2 split-warp
//   (lanes 0-15 resolve q0, lanes 16-31 resolve q1) -> one load + one ballot.
//   Main loop: each pd load feeds both queries' exps; two independent G
//   load streams (64 loads in flight) halve exposed latency per query.
// ---------------------------------------------------------------------------
__global__ void __launch_bounds__(128, 6)
query_kernel(const float* __restrict__ time_tensor,
             const float* __restrict__ past_time,
             const int*   __restrict__ ftc,
             float*       __restrict__ out) {
    int warp_g = (blockIdx.x * blockDim.x + threadIdx.x) >> 5;  // warp id
    int lane   = threadIdx.x & 31;
    int q0     = warp_g * 2;            // queries q0, q0+1
    int b      = q0 >> 10;              // same b for both (1024 even)

    float t0 = time_tensor[q0];
    float t1 = time_tensor[q0 + 1];

    // --- warp-parallel rank for both queries ---
    const float* pt = past_time + b * Tq;
    float v1 = __ldg(&pt[lane * 16 + 15]);               // one load, two ballots
    unsigned m0 = __ballot_sync(0xffffffffu, t0 - v1 > EPSF);
    unsigned m1 = __ballot_sync(0xffffffffu, t1 - v1 > EPSF);
    int full0 = __popc(m0);
    int full1 = __popc(m1);

    // round 2: lanes 0-15 test q0's partial chunk, lanes 16-31 test q1's
    int  myfull = (lane < 16) ? full0 : full1;
    int  safef  = min(myfull, 31);
    float myt   = (lane < 16) ? t0 : t1;
    float v2    = __ldg(&pt[safef * 16 + (lane & 15)]);
    bool  p2    = (myfull < 32) && (myt - v2 > EPSF);
    unsigned m2 = __ballot_sync(0xffffffffu, p2);
    int j0 = full0 * 16 + __popc(m2 & 0xFFFFu);
    int j1 = full1 * 16 + __popc(m2 >> 16);

    const float* G0 = g_table + ((size_t)(b * (Tq + 1) + j0)) * (Cq * Cq);
    const float* G1 = g_table + ((size_t)(b * (Tq + 1) + j1)) * (Cq * Cq);

    // 4-wide FMA trees, two independent streams
    float a00 = 0.f, a01 = 0.f, a02 = 0.f, a03 = 0.f;
    float a10 = 0.f, a11 = 0.f, a12 = 0.f, a13 = 0.f;
    #pragma unroll
    for (int e = 0; e < Cq; e += 4) {
        float pd0 = __ldg(&g_sp_delta[(e + 0) * Cq + lane]);
        float pd1 = __ldg(&g_sp_delta[(e + 1) * Cq + lane]);
        float pd2 = __ldg(&g_sp_delta[(e + 2) * Cq + lane]);
        float pd3 = __ldg(&g_sp_delta[(e + 3) * Cq + lane]);
        a00 = fmaf(__expf(-pd0 * t0), __ldg(&G0[(e + 0) * Cq + lane]), a00);
        a01 = fmaf(__expf(-pd1 * t0), __ldg(&G0[(e + 1) * Cq + lane]), a01);
        a02 = fmaf(__expf(-pd2 * t0), __ldg(&G0[(e + 2) * Cq + lane]), a02);
        a03 = fmaf(__expf(-pd3 * t0), __ldg(&G0[(e + 3) * Cq + lane]), a03);
        a10 = fmaf(__expf(-pd0 * t1), __ldg(&G1[(e + 0) * Cq + lane]), a10);
        a11 = fmaf(__expf(-pd1 * t1), __ldg(&G1[(e + 1) * Cq + lane]), a11);
        a12 = fmaf(__expf(-pd2 * t1), __ldg(&G1[(e + 2) * Cq + lane]), a12);
        a13 = fmaf(__expf(-pd3 * t1), __ldg(&G1[(e + 3) * Cq + lane]), a13);
    }
    float mu_l = __ldg(&g_sp_mu[lane]);
    float acc0 = ((a00 + a01) + (a02 + a03)) + mu_l;
    float acc1 = ((a10 + a11) + (a12 + a13)) + mu_l;

    // Output: out[k] = acc[ftc[k]] * p[k], gather via shuffle (no smem)
    float* o0 = out + (size_t)q0 * Kq;
    float* o1 = o0 + Kq;
    #pragma unroll
    for (int r = 0; r < 4; r++) {
        int   kk = r * 32 + lane;
        int   fc = __ldg(&ftc[kk]);
        float pr = __ldg(&g_probs[kk]);
        float av0 = __shfl_sync(0xffffffffu, acc0, fc);
        float av1 = __shfl_sync(0xffffffffu, acc1, fc);
        o0[kk] = av0 * pr;
        o1[kk] = av1 * pr;
    }
}

// ---------------------------------------------------------------------------
// Launch: 2 graph-capturable kernel launches, no sync, no allocation.
// Input order (metadata): past_event, past_time, time_tensor, mu, alpha,
//                         delta, cf_logits, ftc
// ---------------------------------------------------------------------------
extern "C" void kernel_launch(void* const* d_in, const int* in_sizes, int n_in,
                              void* d_out, int out_size) {
    (void)in_sizes; (void)n_in; (void)out_size;
    const int*   past_event  = (const int*)  d_in[0];
    const float* past_time   = (const float*)d_in[1];
    const float* time_tensor = (const float*)d_in[2];
    const float* mu          = (const float*)d_in[3];
    const float* alpha       = (const float*)d_in[4];
    const float* delta       = (const float*)d_in[5];
    const float* cf          = (const float*)d_in[6];
    const int*   ftc         = (const int*)  d_in[7];
    float*       out         = (float*)d_out;

    table_kernel<<<Bq * Cq, 512>>>(past_event, past_time, alpha, delta, mu, cf, ftc);
    // 4096 queries, 2 per warp, 4 warps per block -> 512 blocks
    query_kernel<<<(Bq * TPq) / 8, 128>>>(time_tensor, past_time, ftc, out);
}